// round 16
// baseline (speedup 1.0000x reference)
#include <cuda_runtime.h>
#include <cuda_fp16.h>
#include <cstdint>

// ---------------------------------------------------------------------------
// QuantizedLinear: y[64,14336] = x[64,8192] @ dequant_int4(w_packed, w_scales)^T + bias
//
// R16: W bypasses shared memory. Each thread LDGs exactly the packed words of
// its mma A-fragments (coalesced 16B groups, both fragment halves in one 32B
// sector -> 1x DRAM), double-buffered one chunk ahead in registers, dequanted
// in-register (exact int4->fp16). Only x (16KB/chunk) flows through the
// cp.async ring, so the per-chunk __syncthreads no longer serializes the
// 235MB weight stream. ROWS=112 -> 128 CTAs (0.875 makespan). 448 thr =
// rg(7) x kg(2); fp32 scale/bias epilogue after a 2-way k-split reduction.
// ---------------------------------------------------------------------------

#define M_TOK   64
#define K_IN    8192
#define N_OUT   14336
#define ROWS    112                 // out-rows per CTA -> 128 CTAs
#define KC      128                 // K per chunk (64 int32 words per row)
#define NCH     (K_IN / KC)         // 64 chunks
#define NSTG    6                   // x-ring stages
#define XSTRIDE 288                 // smem bytes per x row (256 data + 32 pad)
#define XB      (M_TOK * XSTRIDE)   // 18432 per stage
#define SMEM_TOTAL (NSTG * XB)      // 110592
#define NTHREADS 448                // 14 warps: rg(7) x kg(2)

// x as fp16 half2 words, 4096 words per token, permuted within each 8-word
// group as [0,4,1,5,2,6,3,7] so one LDS.64 yields an mma B fragment {b0,b1}.
__device__ __align__(16) uint32_t g_x16[M_TOK * (K_IN / 2)];

// ---------------------------------------------------------------------------
__device__ __forceinline__ uint32_t smem_u32(const void* p) {
    uint32_t a;
    asm("{ .reg .u64 t; cvta.to.shared.u64 t, %1; cvt.u32.u64 %0, t; }" : "=r"(a) : "l"(p));
    return a;
}
__device__ __forceinline__ void cp16(uint32_t dst, const void* src) {
    asm volatile("cp.async.cg.shared.global [%0], [%1], 16;" :: "r"(dst), "l"(src) : "memory");
}
#define CP_COMMIT() asm volatile("cp.async.commit_group;" ::: "memory")

__device__ __forceinline__ void lds64(uint32_t& x, uint32_t& yv, uint32_t a) {
    asm volatile("ld.shared.v2.b32 {%0,%1}, [%2];" : "=r"(x), "=r"(yv) : "r"(a));
}
__device__ __forceinline__ float4 lds128f(uint32_t a) {
    float4 v;
    asm volatile("ld.shared.v4.f32 {%0,%1,%2,%3}, [%4];"
                 : "=f"(v.x), "=f"(v.y), "=f"(v.z), "=f"(v.w) : "r"(a));
    return v;
}
__device__ __forceinline__ void sts128f(uint32_t a, float4 v) {
    asm volatile("st.shared.v4.f32 [%0], {%1,%2,%3,%4};"
                 :: "r"(a), "f"(v.x), "f"(v.y), "f"(v.z), "f"(v.w) : "memory");
}

// int32 holding one packed byte (low nibble = even k, high nibble = odd k)
// -> f16x2 {even k, odd k} with exact signed int4 values.
__device__ __forceinline__ uint32_t nib2h(uint32_t w) {
    uint32_t t = (w | (w << 12)) & 0x000F000Fu;   // SHL + LOP3
    t = (t ^ 0x00080008u) | 0x64006400u;          // LOP3: 1024 + (q^8) per half
    uint32_t r;
    asm("sub.rn.f16x2 %0, %1, %2;" : "=r"(r) : "r"(t), "r"(0x64086408u)); // -1032
    return r;
}

__device__ __forceinline__ void mma16816(float* c,
                                         uint32_t a0, uint32_t a1, uint32_t a2, uint32_t a3,
                                         uint32_t b0, uint32_t b1) {
    asm volatile(
        "mma.sync.aligned.m16n8k16.row.col.f32.f16.f16.f32 "
        "{%0,%1,%2,%3}, {%4,%5,%6,%7}, {%8,%9}, {%0,%1,%2,%3};"
        : "+f"(c[0]), "+f"(c[1]), "+f"(c[2]), "+f"(c[3])
        : "r"(a0), "r"(a1), "r"(a2), "r"(a3), "r"(b0), "r"(b1));
}

// ---------------------------------------------------------------------------
// x fp32 -> fp16 pre-kernel with per-8-word pair permutation.
// Output word p of a token row: group q = p>>3, slot u = p&7,
// original word o = q*8 + ((u>>1) | ((u&1)<<2)).
// ---------------------------------------------------------------------------
__global__ void xconv_kernel(const float* __restrict__ x) {
    int i = blockIdx.x * blockDim.x + threadIdx.x;    // 0 .. 262143
    int tok = i >> 12;
    int p = i & 4095;
    int q = p >> 3, u = p & 7;
    int o = (q << 3) | ((u >> 1) | ((u & 1) << 2));
    float2 v = reinterpret_cast<const float2*>(x)[tok * 4096 + o];
    __half2 h = __floats2half2_rn(v.x, v.y);
    g_x16[i] = *reinterpret_cast<uint32_t*>(&h);
}

// ---------------------------------------------------------------------------
// Main kernel: 128 CTAs x 448 threads (14 warps).
// rg = wid%7 : 16-row group (1 m-tile); kg = wid/7 : 64-k half of each chunk.
// Warp = 16 rows x 64 tokens (8 n-tiles) x 4 k-steps of 16 per chunk.
// W: register-prefetched LDG (no smem). x: cp.async ring in smem.
// ---------------------------------------------------------------------------
__global__ void __launch_bounds__(NTHREADS, 1)
qlin_kernel(const int* __restrict__ wp, const float* __restrict__ ws,
            const float* __restrict__ bias, float* __restrict__ y) {
    extern __shared__ char smem[];
    const uint32_t sb = smem_u32(smem);
    const int tid = threadIdx.x;
    const int wid = tid >> 5, lane = tid & 31;
    const int g = lane >> 2, t = lane & 3;            // mma fragment coords
    const int rg = wid % 7, kg = wid / 7;
    const int row0 = blockIdx.x * ROWS;

    // W base pointers for this thread's two fragment rows (word units), +t folded
    const int* __restrict__ b0p = wp + (size_t)(row0 + rg * 16 + g) * 4096 + t;
    const int* __restrict__ b1p = b0p + 8 * 4096;

    float acc[8][4];                                  // [n-tile][frag]
    #pragma unroll
    for (int j = 0; j < 8; ++j)
        #pragma unroll
        for (int e = 0; e < 4; ++e) acc[j][e] = 0.0f;

    // ---- x fill: 1024 granules of 16B / 448 threads ----
    auto fill = [&](int c, int slot) {
        uint32_t xbase = sb + slot * XB;
        const uint32_t* xsrc = g_x16 + c * 64;               // + tok*4096 below
        #pragma unroll
        for (int it = 0; it < 3; ++it) {
            int id = it * NTHREADS + tid;
            if (id < M_TOK * 16) {
                int tok = id >> 4, gr = id & 15;
                cp16(xbase + tok * XSTRIDE + gr * 16, xsrc + tok * 4096 + gr * 4);
            }
        }
    };

    // ---- W prefetch: 16 LDG.32 into a register buffer (chunk c, this kg half)
    auto prefetch = [&](uint32_t buf[2][8], int c) {
        int off = c * 64 + kg * 32;
        #pragma unroll
        for (int s = 0; s < 4; ++s) {
            buf[0][2 * s]     = (uint32_t)b0p[off + s * 8];
            buf[0][2 * s + 1] = (uint32_t)b0p[off + s * 8 + 4];
            buf[1][2 * s]     = (uint32_t)b1p[off + s * 8];
            buf[1][2 * s + 1] = (uint32_t)b1p[off + s * 8 + 4];
        }
    };

    // ---- consume chunk i: dequant register W + smem x fragments -> 32 mma ----
    auto consume = [&](int i, uint32_t buf[2][8]) {
        uint32_t xbase = sb + (i % NSTG) * XB;
        uint32_t xr0 = xbase + g * XSTRIDE + t * 8 + kg * 128;
        #pragma unroll
        for (int s = 0; s < 4; ++s) {
            uint32_t a0 = nib2h(buf[0][2 * s]);        // row g,   k 2t..
            uint32_t a1 = nib2h(buf[1][2 * s]);        // row g+8
            uint32_t a2 = nib2h(buf[0][2 * s + 1]);    // row g,   k 2t+8..
            uint32_t a3 = nib2h(buf[1][2 * s + 1]);    // row g+8
            #pragma unroll
            for (int j = 0; j < 8; ++j) {
                uint32_t b0, b1;
                lds64(b0, b1, xr0 + j * (8 * XSTRIDE) + s * 32);
                mma16816(acc[j], a0, a1, a2, a3, b0, b1);
            }
        }
    };

    // ---- one pipeline step ----
    auto step = [&](int i, uint32_t cur[2][8], uint32_t nxt[2][8]) {
        asm volatile("cp.async.wait_group %0;" :: "n"(NSTG - 2) : "memory");
        __syncthreads();                       // chunk i's x visible; old slot free
        int cf = i + NSTG - 1;
        if (cf < NCH) fill(cf, cf % NSTG);
        CP_COMMIT();                           // empty group keeps count aligned
        int cp = i + 1 < NCH ? i + 1 : NCH - 1;
        prefetch(nxt, cp);                     // W for chunk i+1 (overlaps mma)
        consume(i, cur);
    };

    // prologue: x chunks 0..NSTG-2 into slots 0..NSTG-2; W chunk 0 into regs
    #pragma unroll
    for (int c = 0; c < NSTG - 1; ++c) { fill(c, c); CP_COMMIT(); }
    uint32_t wA[2][8], wB[2][8];
    prefetch(wA, 0);

    #pragma unroll 1
    for (int i = 0; i < NCH; i += 2) {
        step(i, wA, wB);
        step(i + 1, wB, wA);
    }

    // ---- k-split reduction: kg==1 warps dump partials, kg==0 warps sum ----
    __syncthreads();                           // pipeline done; smem reusable
    uint32_t rb = sb + rg * 4096 + lane * 16;  // 7 warps x 4KB
    if (kg == 1) {
        const float4* af = reinterpret_cast<const float4*>(&acc[0][0]);
        #pragma unroll
        for (int f = 0; f < 8; ++f) sts128f(rb + f * 512, af[f]);
    }
    __syncthreads();

    if (kg == 0) {
        float4* af = reinterpret_cast<float4*>(&acc[0][0]);
        #pragma unroll
        for (int f = 0; f < 8; ++f) {
            float4 p = lds128f(rb + f * 512);
            af[f].x += p.x; af[f].y += p.y; af[f].z += p.z; af[f].w += p.w;
        }

        // ---- epilogue: D * scale + bias (32B-sector stores) ----
        int r = row0 + rg * 16 + g;
        float s0 = ws[r],     b0v = bias[r];
        float s1 = ws[r + 8], b1v = bias[r + 8];
        #pragma unroll
        for (int j = 0; j < 8; ++j) {
            int tok = j * 8 + 2 * t;
            y[(size_t)tok * N_OUT + r]           = acc[j][0] * s0 + b0v;
            y[(size_t)(tok + 1) * N_OUT + r]     = acc[j][1] * s0 + b0v;
            y[(size_t)tok * N_OUT + r + 8]       = acc[j][2] * s1 + b1v;
            y[(size_t)(tok + 1) * N_OUT + r + 8] = acc[j][3] * s1 + b1v;
        }
    }
}

// ---------------------------------------------------------------------------
// Inputs (metadata order): x(f32), w_packed(i32), w_scales(f32), bias(f32)
// ---------------------------------------------------------------------------
extern "C" void kernel_launch(void* const* d_in, const int* in_sizes, int n_in,
                              void* d_out, int out_size) {
    const float* x    = (const float*)d_in[0];
    const int*   wpk  = (const int*)d_in[1];
    const float* wsc  = (const float*)d_in[2];
    const float* bias = (const float*)d_in[3];
    float* y = (float*)d_out;

    cudaFuncSetAttribute(qlin_kernel, cudaFuncAttributeMaxDynamicSharedMemorySize, SMEM_TOTAL);

    xconv_kernel<<<(M_TOK * K_IN / 2) / 256, 256>>>(x);
    qlin_kernel<<<N_OUT / ROWS, NTHREADS, SMEM_TOTAL>>>(wpk, wsc, bias, y);
}